// round 13
// baseline (speedup 1.0000x reference)
#include <cuda_runtime.h>
#include <cuda_bf16.h>

#define NNODES 100000
#define NEDGES 600000
#define DFEAT  128

// Scratch. g_deg is zero on first use (static zero-init) and reset to zero by
// k_dot after reading -> identical initial state every execution.
__device__ float  g_deg[NNODES];   // degree (excl. self loop), self-clearing
__device__ float  g_dis[NNODES];   // rsqrt(1 + deg)
__device__ float  g_p[NNODES];     // p0 = dis * s   (round-1 gather source)
__device__ float2 g_m[NNODES];     // {acc1, dis^2}  (round-1 dest / round-2 source)
__device__ float  g_acc2[NNODES];  // round-2 edge accumulator (zeroed in k_dot)

// K1: degree count, 2 edges/thread
__global__ void k_count_deg(const int* __restrict__ ei) {
    int e = (blockIdx.x * blockDim.x + threadIdx.x) * 2;
    if (e < NEDGES) {
        int2 c2 = *reinterpret_cast<const int2*>(ei + NEDGES + e);
        atomicAdd(&g_deg[c2.x], 1.0f);
        atomicAdd(&g_deg[c2.y], 1.0f);
    }
}

// K2: s = x·w (4 nodes/warp, MLP=4) + full normalization tail:
//     dis = rsqrt(1+deg); deg = 0; p0 = dis*s;
//     g_m = {p0, dis^2}; acc2 = 0
__global__ void k_dot(const float* __restrict__ x, const float* __restrict__ w) {
    int warp_id = (blockIdx.x * blockDim.x + threadIdx.x) >> 5;
    int lane = threadIdx.x & 31;
    int base = warp_id * 4;
    if (base >= NNODES) return;   // NNODES % 4 == 0

    const float4* wr = reinterpret_cast<const float4*>(w);
    float4 wv = __ldg(&wr[lane]);

    float4 xv0 = reinterpret_cast<const float4*>(x + (size_t)(base + 0) * DFEAT)[lane];
    float4 xv1 = reinterpret_cast<const float4*>(x + (size_t)(base + 1) * DFEAT)[lane];
    float4 xv2 = reinterpret_cast<const float4*>(x + (size_t)(base + 2) * DFEAT)[lane];
    float4 xv3 = reinterpret_cast<const float4*>(x + (size_t)(base + 3) * DFEAT)[lane];

    float s0 = xv0.x * wv.x + xv0.y * wv.y + xv0.z * wv.z + xv0.w * wv.w;
    float s1 = xv1.x * wv.x + xv1.y * wv.y + xv1.z * wv.z + xv1.w * wv.w;
    float s2 = xv2.x * wv.x + xv2.y * wv.y + xv2.z * wv.z + xv2.w * wv.w;
    float s3 = xv3.x * wv.x + xv3.y * wv.y + xv3.z * wv.z + xv3.w * wv.w;

    #pragma unroll
    for (int off = 16; off > 0; off >>= 1) {
        s0 += __shfl_xor_sync(0xFFFFFFFFu, s0, off);
        s1 += __shfl_xor_sync(0xFFFFFFFFu, s1, off);
        s2 += __shfl_xor_sync(0xFFFFFFFFu, s2, off);
        s3 += __shfl_xor_sync(0xFFFFFFFFu, s3, off);
    }

    // lanes 0-3: per-node normalization tail (node base+lane)
    if (lane < 4) {
        int i = base + lane;
        float s = (lane == 0) ? s0 : (lane == 1) ? s1 : (lane == 2) ? s2 : s3;
        float d = rsqrtf(1.0f + g_deg[i]);
        g_deg[i]  = 0.0f;                    // self-clear for next execution
        g_dis[i]  = d;
        float p   = d * s;
        g_p[i]    = p;
        g_m[i]    = make_float2(p, d * d);   // acc1 init = self term; dis^2 cached
        g_acc2[i] = 0.0f;
    }
}

// K3: round-1 edges: m[col].x += p0[row]   (1 gather + 1 RED per edge)
__global__ void k_edge1(const int* __restrict__ ei) {
    int e = blockIdx.x * blockDim.x + threadIdx.x;
    if (e < NEDGES) {
        int row = __ldg(&ei[e]);
        int col = __ldg(&ei[NEDGES + e]);
        atomicAdd(&g_m[col].x, __ldg(&g_p[row]));
    }
}

// K4: round-2 edges: acc2[col] += m[row].x * m[row].y
// (one 8B random gather fetches both acc1 and dis^2 -> pre2 pass eliminated)
__global__ void k_edge2(const int* __restrict__ ei) {
    int e = blockIdx.x * blockDim.x + threadIdx.x;
    if (e < NEDGES) {
        int row = __ldg(&ei[e]);
        int col = __ldg(&ei[NEDGES + e]);
        float2 m = __ldg(&g_m[row]);
        atomicAdd(&g_acc2[col], m.x * m.y);
    }
}

// K5: out = dis * (acc2 + self-term) + b,  self-term = acc1 * dis^2
__global__ void k_post(float* __restrict__ out, const float* __restrict__ b) {
    int i = blockIdx.x * blockDim.x + threadIdx.x;
    if (i < NNODES) {
        float2 m = g_m[i];
        out[i] = g_dis[i] * (g_acc2[i] + m.x * m.y) + b[0];
    }
}

extern "C" void kernel_launch(void* const* d_in, const int* in_sizes, int n_in,
                              void* d_out, int out_size) {
    const float* x  = (const float*)d_in[0];
    const int*   ei = (const int*)d_in[1];
    const float* W  = (const float*)d_in[2];
    const float* b  = (const float*)d_in[3];
    float* out = (float*)d_out;

    const int T = 256;
    const int gN   = (NNODES + T - 1) / T;
    const int gE   = (NEDGES + T - 1) / T;        // 1 edge/thread
    const int gE2  = (NEDGES / 2 + T - 1) / T;    // 2 edges/thread
    const int gDot = ((NNODES / 4) * 32 + T - 1) / T;

    k_count_deg<<<gE2, T>>>(ei);
    k_dot<<<gDot, T>>>(x, W);
    k_edge1<<<gE, T>>>(ei);
    k_edge2<<<gE, T>>>(ei);
    k_post<<<gN, T>>>(out, b);
}

// round 15
// speedup vs baseline: 1.3393x; 1.3393x over previous
#include <cuda_runtime.h>
#include <cuda_bf16.h>

#define NNODES 100000
#define NEDGES 600000
#define DFEAT  128

// Scratch. g_deg starts zero (static zero-init) and is reset to zero by k_norm
// after reading -> identical initial state on every execution (deterministic).
__device__ float g_deg[NNODES];    // degree excl. self loop, self-clearing
__device__ float g_dis[NNODES];    // rsqrt(1 + deg)
__device__ float g_s[NNODES];      // raw dot products x·w
__device__ float g_p[NNODES];      // p0 = dis * s
__device__ float g_acc[NNODES];    // round-1 accumulator (init = p0)
__device__ float g_p2[NNODES];     // p1 = dis^2 * acc1
__device__ float g_acc2[NNODES];   // round-2 accumulator (init = p1)

// K1: degree count, 2 edges/thread
__global__ void k_count_deg(const int* __restrict__ ei) {
    int e = (blockIdx.x * blockDim.x + threadIdx.x) * 2;
    if (e < NEDGES) {
        int2 c2 = *reinterpret_cast<const int2*>(ei + NEDGES + e);
        atomicAdd(&g_deg[c2.x], 1.0f);
        atomicAdd(&g_deg[c2.y], 1.0f);
    }
}

// K2: s = x·w per node (4 nodes/warp, MLP=4)
__global__ void k_dot(const float* __restrict__ x, const float* __restrict__ w) {
    int warp_id = (blockIdx.x * blockDim.x + threadIdx.x) >> 5;
    int lane = threadIdx.x & 31;
    int base = warp_id * 4;
    if (base >= NNODES) return;   // NNODES % 4 == 0

    const float4* wr = reinterpret_cast<const float4*>(w);
    float4 wv = __ldg(&wr[lane]);

    float4 xv0 = reinterpret_cast<const float4*>(x + (size_t)(base + 0) * DFEAT)[lane];
    float4 xv1 = reinterpret_cast<const float4*>(x + (size_t)(base + 1) * DFEAT)[lane];
    float4 xv2 = reinterpret_cast<const float4*>(x + (size_t)(base + 2) * DFEAT)[lane];
    float4 xv3 = reinterpret_cast<const float4*>(x + (size_t)(base + 3) * DFEAT)[lane];

    float s0 = xv0.x * wv.x + xv0.y * wv.y + xv0.z * wv.z + xv0.w * wv.w;
    float s1 = xv1.x * wv.x + xv1.y * wv.y + xv1.z * wv.z + xv1.w * wv.w;
    float s2 = xv2.x * wv.x + xv2.y * wv.y + xv2.z * wv.z + xv2.w * wv.w;
    float s3 = xv3.x * wv.x + xv3.y * wv.y + xv3.z * wv.z + xv3.w * wv.w;

    #pragma unroll
    for (int off = 16; off > 0; off >>= 1) {
        s0 += __shfl_xor_sync(0xFFFFFFFFu, s0, off);
        s1 += __shfl_xor_sync(0xFFFFFFFFu, s1, off);
        s2 += __shfl_xor_sync(0xFFFFFFFFu, s2, off);
        s3 += __shfl_xor_sync(0xFFFFFFFFu, s3, off);
    }

    if (lane == 0) {
        *reinterpret_cast<float4*>(&g_s[base]) = make_float4(s0, s1, s2, s3);
    }
}

// K3: dis = rsqrt(1+deg); deg -> 0 (self-clear); p0 = dis*s; acc1 init = p0
__global__ void k_norm() {
    int i = blockIdx.x * blockDim.x + threadIdx.x;
    if (i < NNODES) {
        float d = rsqrtf(1.0f + g_deg[i]);
        g_deg[i] = 0.0f;
        g_dis[i] = d;
        float p = d * g_s[i];
        g_p[i]   = p;
        g_acc[i] = p;
    }
}

// K4: round-1 edges: acc1[col] += p0[row]; 1 edge/thread
__global__ void k_edge1(const int* __restrict__ ei) {
    int e = blockIdx.x * blockDim.x + threadIdx.x;
    if (e < NEDGES) {
        int row = __ldg(&ei[e]);
        int col = __ldg(&ei[NEDGES + e]);
        atomicAdd(&g_acc[col], __ldg(&g_p[row]));
    }
}

// K5: p1 = dis^2 * acc1 ; acc2 init = p1
__global__ void k_pre2() {
    int i = blockIdx.x * blockDim.x + threadIdx.x;
    if (i < NNODES) {
        float dd = g_dis[i];
        float v = dd * dd * g_acc[i];
        g_p2[i]   = v;
        g_acc2[i] = v;
    }
}

// K6: round-2 edges: acc2[col] += p1[row]; 1 edge/thread
__global__ void k_edge2(const int* __restrict__ ei) {
    int e = blockIdx.x * blockDim.x + threadIdx.x;
    if (e < NEDGES) {
        int row = __ldg(&ei[e]);
        int col = __ldg(&ei[NEDGES + e]);
        atomicAdd(&g_acc2[col], __ldg(&g_p2[row]));
    }
}

// K7: out = dis * acc2 + b
__global__ void k_post(float* __restrict__ out, const float* __restrict__ b) {
    int i = blockIdx.x * blockDim.x + threadIdx.x;
    if (i < NNODES) {
        out[i] = g_dis[i] * g_acc2[i] + b[0];
    }
}

extern "C" void kernel_launch(void* const* d_in, const int* in_sizes, int n_in,
                              void* d_out, int out_size) {
    const float* x  = (const float*)d_in[0];
    const int*   ei = (const int*)d_in[1];
    const float* W  = (const float*)d_in[2];
    const float* b  = (const float*)d_in[3];
    float* out = (float*)d_out;

    const int T = 256;
    const int gN   = (NNODES + T - 1) / T;
    const int gE   = (NEDGES + T - 1) / T;        // 1 edge/thread
    const int gE2  = (NEDGES / 2 + T - 1) / T;    // 2 edges/thread
    const int gDot = ((NNODES / 4) * 32 + T - 1) / T;

    k_count_deg<<<gE2, T>>>(ei);
    k_dot<<<gDot, T>>>(x, W);
    k_norm<<<gN, T>>>();
    k_edge1<<<gE, T>>>(ei);
    k_pre2<<<gN, T>>>();
    k_edge2<<<gE, T>>>(ei);
    k_post<<<gN, T>>>(out, b);
}